// round 1
// baseline (speedup 1.0000x reference)
#include <cuda_runtime.h>
#include <cuda_bf16.h>
#include <cstddef>

// Problem constants (fixed shapes)
#define BATCH 8
#define CDIM  64
#define HDIM  256
#define WDIM  256
#define WH    65536            // HDIM*WDIM
#define CWH   (CDIM*WH)        // 4,194,304

// -------------------- scratch (static device globals; no allocation) --------------------
__device__ float g_q [BATCH * CWH];   // q_x
__device__ float g_k [BATCH * CWH];   // k_x
__device__ float g_v [BATCH * CWH];   // v_x + v_a (accumulated)
__device__ float g_qm[BATCH * CWH];   // q_mask
__device__ float g_part1[BATCH * 64 * 4096];  // QK partials (64 K-chunks)
__device__ float g_part2[BATCH * 64 * 4096];
__device__ float g_M[BATCH * 4096];           // A1 + A2

__device__ __forceinline__ float* out_buf(int id) {
    return id == 0 ? g_q : id == 1 ? g_k : id == 2 ? g_v : g_qm;
}

// -------------------- fused depthwise-separable conv --------------------
// One block = one batch x one 16x16 spatial tile, all 64 channels.
// smem: x tile with halo (64x18x18), depthwise out (64x256), pw (64x64), filters.
struct DscP {
    const float* dw;   // (64,1,3,3)
    const float* db;   // (64,)
    const float* pw;   // (64,64) [o][c]
    const float* pb;   // (64,)
    int out_id;        // selects g_q / g_k / g_v / g_qm
};

#define DSC_SMEM_FLOATS (64*324 + 64*256 + 4096 + 576 + 64 + 64)

template <int NPROJ, bool ACCUM>
__global__ __launch_bounds__(256, 1)
void dsc_kernel(const float* __restrict__ in, DscP p0, DscP p1, DscP p2)
{
    extern __shared__ float sm[];
    float* xs    = sm;                 // 64*324
    float* dwout = xs + 64 * 324;      // 64*256
    float* pwsm  = dwout + 64 * 256;   // 4096
    float* fsm   = pwsm + 4096;        // 576
    float* dbsm  = fsm + 576;          // 64
    float* pbsm  = dbsm + 64;          // 64

    const int tid = threadIdx.x;
    const int b   = blockIdx.z;
    const int ty0 = blockIdx.y * 16;
    const int tx0 = blockIdx.x * 16;

    // load input tile with halo (zero pad = SAME)
    const float* inb = in + (size_t)b * CWH;
    for (int idx = tid; idx < 64 * 324; idx += 256) {
        int c = idx / 324, r = idx % 324;
        int yy = r / 18 - 1 + ty0;
        int xx = r % 18 - 1 + tx0;
        float v = 0.0f;
        if (yy >= 0 && yy < HDIM && xx >= 0 && xx < WDIM)
            v = inb[c * WH + yy * WDIM + xx];
        xs[idx] = v;
    }

    DscP ps[3] = {p0, p1, p2};
    const int py = tid / 16, px = tid % 16;
    const int ps64 = tid & 63, og = tid >> 6;

#pragma unroll
    for (int ph = 0; ph < NPROJ; ph++) {
        DscP P = ps[ph];
        __syncthreads();   // previous phase done reading smem (and tile load done)
        for (int i = tid; i < 576; i += 256) fsm[i] = P.dw[i];
        for (int i = tid; i < 4096; i += 256) pwsm[i] = P.pw[i];
        if (tid < 64) { dbsm[tid] = P.db[tid]; pbsm[tid] = P.pb[tid]; }
        __syncthreads();

        // depthwise 3x3 + bias: thread = pixel, loop channels
        for (int c = 0; c < 64; c++) {
            const float* w = fsm + c * 9;
            const float* base = xs + c * 324 + py * 18 + px;
            float s = dbsm[c];
            s += w[0] * base[0]  + w[1] * base[1]  + w[2] * base[2];
            s += w[3] * base[18] + w[4] * base[19] + w[5] * base[20];
            s += w[6] * base[36] + w[7] * base[37] + w[8] * base[38];
            dwout[c * 256 + tid] = s;
        }
        __syncthreads();

        // pointwise 64x64: thread owns 16 outputs x 4 pixels
        float acc[16][4];
#pragma unroll
        for (int i = 0; i < 16; i++) {
            float pbv = pbsm[og * 16 + i];
            acc[i][0] = pbv; acc[i][1] = pbv; acc[i][2] = pbv; acc[i][3] = pbv;
        }
        for (int c = 0; c < 64; c++) {
            float d0 = dwout[c * 256 + ps64];
            float d1 = dwout[c * 256 + ps64 + 64];
            float d2 = dwout[c * 256 + ps64 + 128];
            float d3 = dwout[c * 256 + ps64 + 192];
#pragma unroll
            for (int i = 0; i < 16; i++) {
                float w = pwsm[(og * 16 + i) * 64 + c];
                acc[i][0] += w * d0;
                acc[i][1] += w * d1;
                acc[i][2] += w * d2;
                acc[i][3] += w * d3;
            }
        }
        float* outp = out_buf(P.out_id) + (size_t)b * CWH;
#pragma unroll
        for (int i = 0; i < 16; i++) {
            int o = og * 16 + i;
#pragma unroll
            for (int k = 0; k < 4; k++) {
                int q = ps64 + 64 * k;
                int gy = ty0 + (q >> 4);
                int gx = tx0 + (q & 15);
                size_t gi = (size_t)o * WH + gy * WDIM + gx;
                if (ACCUM) outp[gi] += acc[i][k];
                else       outp[gi]  = acc[i][k];
            }
        }
    }
}

// -------------------- QK: qk[i][j] = sum_p q[i*WH+p] * k[p*64+j] --------------------
// Two GEMMs (q_x and q_m vs same k) fused; deterministic two-stage (partials per chunk).
__global__ __launch_bounds__(256)
void qk_kernel()
{
    const int b = blockIdx.y;
    const int chunk = blockIdx.x;       // 64 chunks of 1024 along p
    const int p0 = chunk * 1024;

    __shared__ float q1s[64 * 33];
    __shared__ float q2s[64 * 33];
    __shared__ float ks [32 * 65];

    const int tid = threadIdx.x;
    const int ti = tid >> 4, tj = tid & 15;
    const int i0 = ti * 4, j0 = tj * 4;

    float acc1[4][4] = {};
    float acc2[4][4] = {};

    const float* qb  = g_q  + (size_t)b * CWH;
    const float* qmb = g_qm + (size_t)b * CWH;
    const float* kb  = g_k  + (size_t)b * CWH;

    for (int kt = 0; kt < 32; kt++) {
        __syncthreads();
        const int pp = p0 + kt * 32;
        for (int e = tid; e < 2048; e += 256) {
            int i = e >> 5, u = e & 31;
            q1s[i * 33 + u] = qb [(size_t)i * WH + pp + u];
            q2s[i * 33 + u] = qmb[(size_t)i * WH + pp + u];
        }
        for (int e = tid; e < 2048; e += 256) {
            int u = e >> 6, j = e & 63;
            ks[u * 65 + j] = kb[(size_t)(pp + u) * 64 + j];
        }
        __syncthreads();
#pragma unroll 4
        for (int u = 0; u < 32; u++) {
            float a1[4], a2[4], bv[4];
#pragma unroll
            for (int r = 0; r < 4; r++) {
                a1[r] = q1s[(i0 + r) * 33 + u];
                a2[r] = q2s[(i0 + r) * 33 + u];
            }
#pragma unroll
            for (int s = 0; s < 4; s++) bv[s] = ks[u * 65 + j0 + s];
#pragma unroll
            for (int r = 0; r < 4; r++)
#pragma unroll
                for (int s = 0; s < 4; s++) {
                    acc1[r][s] += a1[r] * bv[s];
                    acc2[r][s] += a2[r] * bv[s];
                }
        }
    }

    float* P1 = g_part1 + ((size_t)b * 64 + chunk) * 4096;
    float* P2 = g_part2 + ((size_t)b * 64 + chunk) * 4096;
#pragma unroll
    for (int r = 0; r < 4; r++)
#pragma unroll
        for (int s = 0; s < 4; s++) {
            P1[(i0 + r) * 64 + j0 + s] = acc1[r][s];
            P2[(i0 + r) * 64 + j0 + s] = acc2[r][s];
        }
}

// -------------------- reduce partials + softmax(flattened 4096) + M = A1+A2 ----------
__global__ __launch_bounds__(256)
void softmax_kernel()
{
    __shared__ float buf[4096];
    __shared__ float red[256];
    const int b = blockIdx.x;
    const int tid = threadIdx.x;

    for (int m = 0; m < 2; m++) {
        const float* part = (m == 0 ? g_part1 : g_part2) + (size_t)b * 64 * 4096;
        __syncthreads();
        float lmax = -1e30f;
        for (int e = tid; e < 4096; e += 256) {
            float s = 0.0f;
            for (int ch = 0; ch < 64; ch++) s += part[(size_t)ch * 4096 + e];
            s *= (1.0f / 256.0f);    // 1/sqrt(WH)
            buf[e] = s;
            lmax = fmaxf(lmax, s);
        }
        red[tid] = lmax; __syncthreads();
        for (int s = 128; s; s >>= 1) {
            if (tid < s) red[tid] = fmaxf(red[tid], red[tid + s]);
            __syncthreads();
        }
        float mx = red[0];
        __syncthreads();

        float lsum = 0.0f;
        for (int e = tid; e < 4096; e += 256) {
            float ev = __expf(buf[e] - mx);
            buf[e] = ev;
            lsum += ev;
        }
        red[tid] = lsum; __syncthreads();
        for (int s = 128; s; s >>= 1) {
            if (tid < s) red[tid] += red[tid + s];
            __syncthreads();
        }
        float inv = 1.0f / red[0];

        for (int e = tid; e < 4096; e += 256) {
            float val = buf[e] * inv;
            float* mp = g_M + (size_t)b * 4096 + e;
            if (m == 0) *mp = val;
            else        *mp += val;
        }
    }
}

// -------------------- out = M @ v_sum + x --------------------
__global__ __launch_bounds__(256)
void out_kernel(const float* __restrict__ x, float* __restrict__ out)
{
    __shared__ float Msm[4096];
    const int b = blockIdx.y;
    const int p0 = blockIdx.x * 256;
    const int tid = threadIdx.x;

    for (int e = tid; e < 4096; e += 256) Msm[e] = g_M[(size_t)b * 4096 + e];
    __syncthreads();

    const int ps64 = tid & 63, cg = tid >> 6;
    const float* vb = g_v + (size_t)b * CWH + p0 + ps64;

    float acc[16][4] = {};
#pragma unroll 4
    for (int j = 0; j < 64; j++) {
        float v0 = vb[(size_t)j * WH];
        float v1 = vb[(size_t)j * WH + 64];
        float v2 = vb[(size_t)j * WH + 128];
        float v3 = vb[(size_t)j * WH + 192];
#pragma unroll
        for (int i = 0; i < 16; i++) {
            float mv = Msm[(cg * 16 + i) * 64 + j];
            acc[i][0] += mv * v0;
            acc[i][1] += mv * v1;
            acc[i][2] += mv * v2;
            acc[i][3] += mv * v3;
        }
    }

    const float* xb = x + (size_t)b * CWH + p0 + ps64;
    float* ob = out + (size_t)b * CWH + p0 + ps64;
#pragma unroll
    for (int i = 0; i < 16; i++) {
        int ch = cg * 16 + i;
#pragma unroll
        for (int k = 0; k < 4; k++) {
            size_t gi = (size_t)ch * WH + 64 * k;
            ob[gi] = acc[i][k] + xb[gi];
        }
    }
}

// -------------------- launch --------------------
extern "C" void kernel_launch(void* const* d_in, const int* in_sizes, int n_in,
                              void* d_out, int out_size)
{
    const float* x    = (const float*)d_in[0];
    const float* mask = (const float*)d_in[1];
    const float* avg  = (const float*)d_in[2];
    DscP q = { (const float*)d_in[3],  (const float*)d_in[4],
               (const float*)d_in[5],  (const float*)d_in[6],  0 };
    DscP k = { (const float*)d_in[7],  (const float*)d_in[8],
               (const float*)d_in[9],  (const float*)d_in[10], 1 };
    DscP v = { (const float*)d_in[11], (const float*)d_in[12],
               (const float*)d_in[13], (const float*)d_in[14], 2 };
    DscP qm = q; qm.out_id = 3;   // mask -> q_m (same q weights)
    float* out = (float*)d_out;

    const size_t dsc_smem = DSC_SMEM_FLOATS * sizeof(float);
    cudaFuncSetAttribute(dsc_kernel<3, false>, cudaFuncAttributeMaxDynamicSharedMemorySize, (int)dsc_smem);
    cudaFuncSetAttribute(dsc_kernel<1, false>, cudaFuncAttributeMaxDynamicSharedMemorySize, (int)dsc_smem);
    cudaFuncSetAttribute(dsc_kernel<1, true>,  cudaFuncAttributeMaxDynamicSharedMemorySize, (int)dsc_smem);

    dim3 dscGrid(WDIM / 16, HDIM / 16, BATCH);

    // x -> q_x, k_x, v_x (one tile load, three projections)
    dsc_kernel<3, false><<<dscGrid, 256, dsc_smem>>>(x, q, k, v);
    // mask -> q_m
    dsc_kernel<1, false><<<dscGrid, 256, dsc_smem>>>(mask, qm, qm, qm);
    // avg_ct -> v_a, accumulated into g_v (v_sum = v_x + v_a)
    dsc_kernel<1, true><<<dscGrid, 256, dsc_smem>>>(avg, v, v, v);

    // QK partials (both A1 and A2 pre-softmax, deterministic)
    qk_kernel<<<dim3(64, BATCH), 256>>>();

    // reduce + softmax(flat 4096) + M = A1 + A2
    softmax_kernel<<<BATCH, 256>>>();

    // out = M @ v_sum + x
    out_kernel<<<dim3(WH / 256, BATCH), 256>>>(x, out);
}

// round 2
// speedup vs baseline: 1.5547x; 1.5547x over previous
#include <cuda_runtime.h>
#include <cuda_bf16.h>
#include <cstddef>

#define BATCH 8
#define CDIM  64
#define HDIM  256
#define WDIM  256
#define WH    65536
#define CWH   (CDIM*WH)

// -------------------- scratch --------------------
__device__ float g_q [BATCH * CWH];
__device__ float g_k [BATCH * CWH];
__device__ float g_v [BATCH * CWH];
__device__ float g_qm[BATCH * CWH];
__device__ float g_part1[BATCH * 64 * 4096];
__device__ float g_part2[BATCH * 64 * 4096];
__device__ float g_R1[BATCH * 4096];
__device__ float g_R2[BATCH * 4096];
__device__ float g_M[BATCH * 4096];

__device__ __forceinline__ float* out_buf(int id) {
    return id == 0 ? g_q : id == 1 ? g_k : id == 2 ? g_v : g_qm;
}

// -------------------- f32x2 helpers --------------------
typedef unsigned long long u64t;
__device__ __forceinline__ u64t pk2(float lo, float hi) {
    u64t r; asm("mov.b64 %0, {%1,%2};" : "=l"(r) : "f"(lo), "f"(hi)); return r;
}
__device__ __forceinline__ void unpk(u64t a, float& x, float& y) {
    asm("mov.b64 {%0,%1}, %2;" : "=f"(x), "=f"(y) : "l"(a));
}
__device__ __forceinline__ u64t fma2(u64t a, u64t b, u64t c) {
    u64t d; asm("fma.rn.f32x2 %0, %1, %2, %3;" : "=l"(d) : "l"(a), "l"(b), "l"(c)); return d;
}
__device__ __forceinline__ u64t add2(u64t a, u64t b) {
    u64t d; asm("add.rn.f32x2 %0, %1, %2;" : "=l"(d) : "l"(a), "l"(b)); return d;
}

// -------------------- cp.async helpers --------------------
__device__ __forceinline__ void cp16(void* s, const void* g) {
    unsigned sa = (unsigned)__cvta_generic_to_shared(s);
    asm volatile("cp.async.cg.shared.global [%0], [%1], 16;\n" :: "r"(sa), "l"(g));
}
__device__ __forceinline__ void cp_commit() { asm volatile("cp.async.commit_group;\n"); }
template<int N> __device__ __forceinline__ void cp_wait() {
    asm volatile("cp.async.wait_group %0;\n" :: "n"(N));
}

// -------------------- fused depthwise-separable conv --------------------
struct DscP {
    const float* dw;
    const float* db;
    const float* pw;   // (64,64) [o][c]
    const float* pb;
    int out_id;
};

// smem floats: xs 20736 + dwout 16384 + pwq 8192 + fsm 576 + dbsm 64 + pbsm 64
#define DSC_SMEM_FLOATS (20736 + 16384 + 8192 + 576 + 64 + 64)

template <int NPROJ, bool ACCUM>
__global__ __launch_bounds__(512, 1)
void dsc_kernel(const float* __restrict__ in, DscP p0, DscP p1, DscP p2)
{
    extern __shared__ float sm[];
    float* xs    = sm;                 // 64 x 18 x 18
    float* dwout = xs + 20736;         // 64 x 256
    float* pwq   = dwout + 16384;      // 64 x 32 float4 (w,w,w',w')
    float* fsm   = pwq + 8192;         // 576
    float* dbsm  = fsm + 576;          // 64
    float* pbsm  = dbsm + 64;          // 64

    const int tid = threadIdx.x;
    const int b   = blockIdx.z;
    const int ty0 = blockIdx.y * 16;
    const int tx0 = blockIdx.x * 16;

    // tile load with halo
    const float* inb = in + (size_t)b * CWH;
    for (int idx = tid; idx < 20736; idx += 512) {
        int c = idx / 324, r = idx % 324;
        int yy = r / 18 - 1 + ty0;
        int xx = r % 18 - 1 + tx0;
        float v = 0.0f;
        if (yy >= 0 && yy < HDIM && xx >= 0 && xx < WDIM)
            v = inb[c * WH + yy * WDIM + xx];
        xs[idx] = v;
    }

    DscP ps[3] = {p0, p1, p2};
    // depthwise ids: 2 adjacent pixels per thread, 4 channel slices
    const int px2  = tid & 127;
    const int c0   = tid >> 7;          // 0..3
    const int drow = (2 * px2) >> 4;
    const int dcol = (2 * px2) & 15;    // even
    // pointwise ids
    const int pp = tid & 63;
    const int og = tid >> 6;            // 0..7

#pragma unroll
    for (int ph = 0; ph < NPROJ; ph++) {
        DscP P = ps[ph];
        __syncthreads();
        for (int i = tid; i < 576; i += 512) fsm[i] = P.dw[i];
        for (int idx = tid; idx < 2048; idx += 512) {
            int o = idx >> 5, cc = idx & 31;
            float w0 = P.pw[o * 64 + 2 * cc];
            float w1 = P.pw[o * 64 + 2 * cc + 1];
            ((float4*)pwq)[idx] = make_float4(w0, w0, w1, w1);
        }
        if (tid < 64) { dbsm[tid] = P.db[tid]; pbsm[tid] = P.pb[tid]; }
        __syncthreads();

        // depthwise 3x3 + bias, 2 pixels per thread
        for (int c = c0; c < 64; c += 4) {
            const float* base = xs + c * 324 + drow * 18 + dcol;
            float r[3][4];
#pragma unroll
            for (int dy = 0; dy < 3; dy++) {
                float2 a  = *(const float2*)(base + dy * 18);
                float2 b2 = *(const float2*)(base + dy * 18 + 2);
                r[dy][0] = a.x; r[dy][1] = a.y; r[dy][2] = b2.x; r[dy][3] = b2.y;
            }
            const float* w = fsm + c * 9;
            float s0 = dbsm[c], s1 = s0;
#pragma unroll
            for (int dy = 0; dy < 3; dy++) {
                s0 += w[3*dy] * r[dy][0] + w[3*dy+1] * r[dy][1] + w[3*dy+2] * r[dy][2];
                s1 += w[3*dy] * r[dy][1] + w[3*dy+1] * r[dy][2] + w[3*dy+2] * r[dy][3];
            }
            *(float2*)&dwout[c * 256 + 2 * px2] = make_float2(s0, s1);
        }
        __syncthreads();

        // pointwise 64x64 with FFMA2: thread = 8 outputs x 2 pixel-pairs
        u64t acc[8][2];
#pragma unroll
        for (int i = 0; i < 8; i++) {
            float pbv = pbsm[og * 8 + i];
            acc[i][0] = pk2(pbv, pbv);
            acc[i][1] = acc[i][0];
        }
        for (int cc = 0; cc < 32; cc++) {
            int c2 = 2 * cc;
            u64t dA0 = *(const u64t*)&dwout[c2 * 256 + 2 * pp];
            u64t dA1 = *(const u64t*)&dwout[c2 * 256 + 128 + 2 * pp];
            u64t dB0 = *(const u64t*)&dwout[(c2 + 1) * 256 + 2 * pp];
            u64t dB1 = *(const u64t*)&dwout[(c2 + 1) * 256 + 128 + 2 * pp];
#pragma unroll
            for (int i = 0; i < 8; i++) {
                ulonglong2 w2 = *(const ulonglong2*)&pwq[((og * 8 + i) * 32 + cc) * 4];
                acc[i][0] = fma2(w2.x, dA0, acc[i][0]);
                acc[i][1] = fma2(w2.x, dA1, acc[i][1]);
                acc[i][0] = fma2(w2.y, dB0, acc[i][0]);
                acc[i][1] = fma2(w2.y, dB1, acc[i][1]);
            }
        }

        // store: pixel pairs (2pp, 2pp+1) and (128+2pp, 129+2pp)
        float* outp = out_buf(P.out_id) + (size_t)b * CWH;
        const int q0 = 2 * pp;
        const int gy0 = ty0 + (q0 >> 4), gx0 = tx0 + (q0 & 15);
        const size_t base0 = (size_t)gy0 * WDIM + gx0;
#pragma unroll
        for (int i = 0; i < 8; i++) {
            int o = og * 8 + i;
            size_t gi0 = (size_t)o * WH + base0;
            size_t gi1 = gi0 + 8 * WDIM;   // pixel +128 => +8 rows
            if (ACCUM) {
                u64t x0 = *(const u64t*)&outp[gi0];
                u64t x1 = *(const u64t*)&outp[gi1];
                *(u64t*)&outp[gi0] = add2(acc[i][0], x0);
                *(u64t*)&outp[gi1] = add2(acc[i][1], x1);
            } else {
                *(u64t*)&outp[gi0] = acc[i][0];
                *(u64t*)&outp[gi1] = acc[i][1];
            }
        }
    }
}

// -------------------- QK with cp.async double buffer + FFMA2 --------------------
#define QSTR 36
#define KSTR 68

__global__ __launch_bounds__(256)
void qk_kernel()
{
    const int b = blockIdx.y;
    const int chunk = blockIdx.x;
    const int p0 = chunk * 1024;
    const int tid = threadIdx.x;
    const int ti = tid >> 4, tj = tid & 15;
    const int i0 = ti * 4, j0 = tj * 4;

    __shared__ __align__(16) float q1s[2][64 * QSTR];
    __shared__ __align__(16) float q2s[2][64 * QSTR];
    __shared__ __align__(16) float ks [2][32 * KSTR];

    const float* qb  = g_q  + (size_t)b * CWH;
    const float* qmb = g_qm + (size_t)b * CWH;
    const float* kb  = g_k  + (size_t)b * CWH;

    auto prefetch = [&](int kt, int s) {
        const int pp2 = p0 + kt * 32;
        for (int e = tid; e < 512; e += 256) {
            int i = e >> 3, u4 = (e & 7) * 4;
            cp16(&q1s[s][i * QSTR + u4], qb  + (size_t)i * WH + pp2 + u4);
            cp16(&q2s[s][i * QSTR + u4], qmb + (size_t)i * WH + pp2 + u4);
        }
        for (int e = tid; e < 512; e += 256) {
            int u = e >> 4, j4 = (e & 15) * 4;
            cp16(&ks[s][u * KSTR + j4], kb + (size_t)(pp2 + u) * 64 + j4);
        }
        cp_commit();
    };

    u64t acc1[4][2] = {};
    u64t acc2[4][2] = {};

    prefetch(0, 0);
    prefetch(1, 1);

    for (int kt = 0; kt < 32; kt++) {
        if (kt == 31) cp_wait<0>(); else cp_wait<1>();
        __syncthreads();
        const int cur = kt & 1;
#pragma unroll 2
        for (int u = 0; u < 32; u++) {
            ulonglong2 bv = *(const ulonglong2*)&ks[cur][u * KSTR + j0];
#pragma unroll
            for (int r = 0; r < 4; r++) {
                float av1 = q1s[cur][(i0 + r) * QSTR + u];
                u64t a1d = pk2(av1, av1);
                acc1[r][0] = fma2(a1d, bv.x, acc1[r][0]);
                acc1[r][1] = fma2(a1d, bv.y, acc1[r][1]);
                float av2 = q2s[cur][(i0 + r) * QSTR + u];
                u64t a2d = pk2(av2, av2);
                acc2[r][0] = fma2(a2d, bv.x, acc2[r][0]);
                acc2[r][1] = fma2(a2d, bv.y, acc2[r][1]);
            }
        }
        __syncthreads();
        if (kt + 2 < 32) prefetch(kt + 2, cur);
    }

    float* P1 = g_part1 + ((size_t)b * 64 + chunk) * 4096;
    float* P2 = g_part2 + ((size_t)b * 64 + chunk) * 4096;
#pragma unroll
    for (int r = 0; r < 4; r++) {
        float a, bb, c, d;
        unpk(acc1[r][0], a, bb); unpk(acc1[r][1], c, d);
        *(float4*)&P1[(i0 + r) * 64 + j0] = make_float4(a, bb, c, d);
        unpk(acc2[r][0], a, bb); unpk(acc2[r][1], c, d);
        *(float4*)&P2[(i0 + r) * 64 + j0] = make_float4(a, bb, c, d);
    }
}

// -------------------- parallel partial reduce --------------------
__global__ __launch_bounds__(512)
void reduce_kernel()
{
    const int b = blockIdx.y;
    const int e = blockIdx.x * 512 + threadIdx.x;   // grid.x = 8 -> 4096
    const float* P1 = g_part1 + (size_t)b * 64 * 4096;
    const float* P2 = g_part2 + (size_t)b * 64 * 4096;
    float s1 = 0.0f, s2 = 0.0f;
#pragma unroll 8
    for (int ch = 0; ch < 64; ch++) {
        s1 += P1[(size_t)ch * 4096 + e];
        s2 += P2[(size_t)ch * 4096 + e];
    }
    g_R1[(size_t)b * 4096 + e] = s1 * (1.0f / 256.0f);
    g_R2[(size_t)b * 4096 + e] = s2 * (1.0f / 256.0f);
}

// -------------------- softmax(flat 4096) x2 + M = A1+A2 --------------------
__global__ __launch_bounds__(256)
void softmax_kernel()
{
    __shared__ float buf[4096];
    __shared__ float red[256];
    const int b = blockIdx.x;
    const int tid = threadIdx.x;

    for (int m = 0; m < 2; m++) {
        const float* R = (m == 0 ? g_R1 : g_R2) + (size_t)b * 4096;
        __syncthreads();
        float lmax = -1e30f;
        for (int e = tid; e < 4096; e += 256) {
            float s = R[e];
            buf[e] = s;
            lmax = fmaxf(lmax, s);
        }
        red[tid] = lmax; __syncthreads();
        for (int s = 128; s; s >>= 1) {
            if (tid < s) red[tid] = fmaxf(red[tid], red[tid + s]);
            __syncthreads();
        }
        float mx = red[0];
        __syncthreads();

        float lsum = 0.0f;
        for (int e = tid; e < 4096; e += 256) {
            float ev = __expf(buf[e] - mx);
            buf[e] = ev;
            lsum += ev;
        }
        red[tid] = lsum; __syncthreads();
        for (int s = 128; s; s >>= 1) {
            if (tid < s) red[tid] += red[tid + s];
            __syncthreads();
        }
        float inv = 1.0f / red[0];

        for (int e = tid; e < 4096; e += 256) {
            float val = buf[e] * inv;
            float* mp = g_M + (size_t)b * 4096 + e;
            if (m == 0) *mp = val;
            else        *mp += val;
        }
    }
}

// -------------------- out = M @ v_sum + x (FFMA2) --------------------
__global__ __launch_bounds__(512)
void out_kernel(const float* __restrict__ x, float* __restrict__ out)
{
    __shared__ __align__(16) float mq[8192];   // 64 x 32 float4 (m,m,m',m')
    const int b = blockIdx.y;
    const int p0 = blockIdx.x * 256;
    const int tid = threadIdx.x;

    for (int idx = tid; idx < 2048; idx += 512) {
        int o = idx >> 5, cc = idx & 31;
        float m0 = g_M[(size_t)b * 4096 + o * 64 + 2 * cc];
        float m1 = g_M[(size_t)b * 4096 + o * 64 + 2 * cc + 1];
        ((float4*)mq)[idx] = make_float4(m0, m0, m1, m1);
    }
    __syncthreads();

    const int pp = tid & 63, og = tid >> 6;
    const float* vb = g_v + (size_t)b * CWH + p0 + 2 * pp;

    u64t acc[8][2] = {};
    for (int cc = 0; cc < 32; cc++) {
        int c2 = 2 * cc;
        u64t v00 = *(const u64t*)(vb + (size_t)c2 * WH);
        u64t v01 = *(const u64t*)(vb + (size_t)c2 * WH + 128);
        u64t v10 = *(const u64t*)(vb + (size_t)(c2 + 1) * WH);
        u64t v11 = *(const u64t*)(vb + (size_t)(c2 + 1) * WH + 128);
#pragma unroll
        for (int i = 0; i < 8; i++) {
            ulonglong2 w2 = *(const ulonglong2*)&mq[((og * 8 + i) * 32 + cc) * 4];
            acc[i][0] = fma2(w2.x, v00, acc[i][0]);
            acc[i][1] = fma2(w2.x, v01, acc[i][1]);
            acc[i][0] = fma2(w2.y, v10, acc[i][0]);
            acc[i][1] = fma2(w2.y, v11, acc[i][1]);
        }
    }

    const float* xb = x + (size_t)b * CWH + p0 + 2 * pp;
    float* ob = out + (size_t)b * CWH + p0 + 2 * pp;
#pragma unroll
    for (int i = 0; i < 8; i++) {
        int o = og * 8 + i;
        u64t x0 = *(const u64t*)(xb + (size_t)o * WH);
        u64t x1 = *(const u64t*)(xb + (size_t)o * WH + 128);
        *(u64t*)(ob + (size_t)o * WH)       = add2(acc[i][0], x0);
        *(u64t*)(ob + (size_t)o * WH + 128) = add2(acc[i][1], x1);
    }
}

// -------------------- launch --------------------
extern "C" void kernel_launch(void* const* d_in, const int* in_sizes, int n_in,
                              void* d_out, int out_size)
{
    const float* x    = (const float*)d_in[0];
    const float* mask = (const float*)d_in[1];
    const float* avg  = (const float*)d_in[2];
    DscP q = { (const float*)d_in[3],  (const float*)d_in[4],
               (const float*)d_in[5],  (const float*)d_in[6],  0 };
    DscP k = { (const float*)d_in[7],  (const float*)d_in[8],
               (const float*)d_in[9],  (const float*)d_in[10], 1 };
    DscP v = { (const float*)d_in[11], (const float*)d_in[12],
               (const float*)d_in[13], (const float*)d_in[14], 2 };
    DscP qm = q; qm.out_id = 3;
    float* out = (float*)d_out;

    const size_t dsc_smem = DSC_SMEM_FLOATS * sizeof(float);
    cudaFuncSetAttribute(dsc_kernel<3, false>, cudaFuncAttributeMaxDynamicSharedMemorySize, (int)dsc_smem);
    cudaFuncSetAttribute(dsc_kernel<1, false>, cudaFuncAttributeMaxDynamicSharedMemorySize, (int)dsc_smem);
    cudaFuncSetAttribute(dsc_kernel<1, true>,  cudaFuncAttributeMaxDynamicSharedMemorySize, (int)dsc_smem);

    dim3 dscGrid(WDIM / 16, HDIM / 16, BATCH);

    dsc_kernel<3, false><<<dscGrid, 512, dsc_smem>>>(x, q, k, v);
    dsc_kernel<1, false><<<dscGrid, 512, dsc_smem>>>(mask, qm, qm, qm);
    dsc_kernel<1, true><<<dscGrid, 512, dsc_smem>>>(avg, v, v, v);

    qk_kernel<<<dim3(64, BATCH), 256>>>();
    reduce_kernel<<<dim3(8, BATCH), 512>>>();
    softmax_kernel<<<BATCH, 256>>>();
    out_kernel<<<dim3(WH / 256, BATCH), 512>>>(x, out);
}